// round 16
// baseline (speedup 1.0000x reference)
#include <cuda_runtime.h>
#include <math_constants.h>
#include <cstdint>

// Problem: B=128, L=4096, FILTER_SIZE=2, N_QUBITS=4, 10 classes.
// Analytic reduction: expval_k(b,ol) = K_k * g(b,ol),
//   K_k = cos(p_k1)cos(p_k2)cos(p_k3)   (CNOT ring conjugates Z0 -> Z1Z2Z3)
//   g   = cos(x[ol,1]) * cos(x[ol+1,0]) * cos(x[ol+1,1])
// logits[j] = bias[j] + sum_ol g(ol)*(K0*W[2ol,j]+K1*W[2ol+1,j]); softmax.
//
// SINGLE heterogeneous grid (saves one ~5000-cycle launch overhead + gap):
//   blocks 0-31  : producer blocks -> fold Wp columns [128p, 128p+128)
//   blocks 32-159: R4 main blocks (one row each); warp w polls ONLY flag[w]
// (warp w consumes exactly the columns producer block w wrote).
#define OLP    4096
#define NCLS   10
#define B_SZ   128
#define NPREP  32
#define NT     1024
#define NWARP  (NT / 32)
#define W_F4   20475          // float4 count of W (8190*10 floats)

// Folded, TRANSPOSED weights d_Wp[j*OLP + ol]; column 4095 folds to zero.
__device__ __align__(16) float d_Wp[NCLS * OLP];
// Per-slice publish flags + finish ticket (zero at load; kernel re-zeroes).
__device__ int d_flag[NPREP];
__device__ int d_fin;

__global__ __launch_bounds__(NT, 1)
void qcnn_hetero(const float* __restrict__ x, const float* __restrict__ params,
                 const float* __restrict__ W, const float* __restrict__ bias,
                 float* __restrict__ out)
{
    const int bid  = blockIdx.x;
    const int tid  = threadIdx.x;
    const int lane = tid & 31;
    const int warp = tid >> 5;

    if (bid < NPREP) {
        // ===== producer block p: fold Wp columns [128p, 128p+128) =====
        __shared__ __align__(16) float sw[2560];        // 640 raw W float4
        const int p = bid;
        if (tid < 640) {                                // coalesced stage
            int gi = 640 * p + tid;
            ((float4*)sw)[tid] = (gi < W_F4) ? ((const float4*)W)[gi]
                                             : make_float4(0.f, 0.f, 0.f, 0.f);
        }
        __syncthreads();
        if (tid < 128) {
            float K0 = __cosf(params[1]) * __cosf(params[2]) * __cosf(params[3]);
            float K1 = __cosf(params[5]) * __cosf(params[6]) * __cosf(params[7]);
            int ol = 128 * p + tid;
            const float* r = &sw[20 * tid];             // rows 2ol, 2ol+1
#pragma unroll
            for (int j = 0; j < NCLS; ++j)              // coalesced 512B STG
                d_Wp[j * OLP + ol] = fmaf(K1, r[10 + j], K0 * r[j]);
            __threadfence();                            // publish stores
        }
        __syncthreads();                                // all fences done
        if (tid == 0) atomicExch(&d_flag[p], 1);        // slice p ready
    } else {
        // ===== main block: one batch row, R4-exact math =====
        __shared__ float sred[NWARP][NCLS];
        const int b = bid - NPREP;

        // phase 1: x pairs 4t..4t+3 (two float4 per thread)
        const float* xr = x + (size_t)b * OLP * 2;
        const float4* row4 = (const float4*)xr;
        float4 v0 = row4[2 * tid];
        float4 v1 = row4[2 * tid + 1];

        float nx = __shfl_down_sync(0xFFFFFFFFu, v0.x, 1);
        float ny = __shfl_down_sync(0xFFFFFFFFu, v0.y, 1);
        if (lane == 31) {
            int off = (tid == NT - 1) ? 0 : 8 * tid + 8;   // tid=1023: unused
            float2 nb = *(const float2*)(xr + off);
            nx = nb.x; ny = nb.y;
        }

        float s1_0 = __cosf(v0.y);
        float s1_1 = __cosf(v0.w), h1 = __cosf(v0.z) * s1_1;
        float s1_2 = __cosf(v1.y), h2 = __cosf(v1.x) * s1_2;
        float s1_3 = __cosf(v1.w), h3 = __cosf(v1.z) * s1_3;
        float h4   = __cosf(nx)   * __cosf(ny);
        float g0 = s1_0 * h1;
        float g1 = s1_1 * h2;
        float g2 = s1_2 * h3;
        float g3 = (tid == NT - 1) ? 0.0f : s1_3 * h4;  // window 4095 pad

        // per-warp wait: warp w reads only columns [128w,128w+128) = slice w
        if (lane == 0) {
            while (atomicAdd(&d_flag[warp], 0) == 0) { }
        }
        __syncwarp();

        // dot with folded weights: 10 coalesced LDG.128 (MLP=10, L2-hot)
        const float4* Wp4 = (const float4*)d_Wp;
        float acc[NCLS];
#pragma unroll
        for (int j = 0; j < NCLS; ++j) {
            float4 w = Wp4[j * (OLP / 4) + tid];
            float a;
            a = g0 * w.x;
            a = fmaf(g1, w.y, a);
            a = fmaf(g2, w.z, a);
            a = fmaf(g3, w.w, a);
            acc[j] = a;
        }

        // reduce 1024 threads -> 10 logits (R4 butterfly)
#pragma unroll
        for (int j = 0; j < NCLS; ++j) {
#pragma unroll
            for (int off = 16; off; off >>= 1)
                acc[j] += __shfl_xor_sync(0xFFFFFFFFu, acc[j], off);
        }
        if (lane == 0) {
#pragma unroll
            for (int j = 0; j < NCLS; ++j) sred[warp][j] = acc[j];
        }
        __syncthreads();

        // final reduce + softmax in warp 0 (lanes 0..9 own one class)
        if (tid < 32) {
            float logit = -CUDART_INF_F;
            if (tid < NCLS) {
                logit = bias[tid];
#pragma unroll
                for (int w = 0; w < NWARP; ++w) logit += sred[w][tid];
            }
            float mx = logit;
#pragma unroll
            for (int off = 16; off; off >>= 1)
                mx = fmaxf(mx, __shfl_xor_sync(0xFFFFFFFFu, mx, off));
            float e = (tid < NCLS) ? __expf(logit - mx) : 0.0f;
            float s = e;
#pragma unroll
            for (int off = 16; off; off >>= 1)
                s += __shfl_xor_sync(0xFFFFFFFFu, s, off);
            if (tid < NCLS) out[b * NCLS + tid] = e / s;
        }
    }

    // ===== last of all 160 blocks resets flags + ticket (replay-safe:
    // nobody polls flags after their dot phase; reset runs after ALL done)
    if (tid == 0) {
        if (atomicAdd(&d_fin, 1) == (B_SZ + NPREP) - 1) {
#pragma unroll
            for (int i = 0; i < NPREP; ++i) d_flag[i] = 0;
            d_fin = 0;
            __threadfence();
        }
    }
}

// Inputs (metadata order): inputs(128*4096*2 f32), params(8 f32),
//                          W(8190*10 f32), b(10 f32). Output: (128*10) f32.
extern "C" void kernel_launch(void* const* d_in, const int* in_sizes, int n_in,
                              void* d_out, int out_size)
{
    const float* inputs = (const float*)d_in[0];
    const float* params = (const float*)d_in[1];
    const float* W      = (const float*)d_in[2];
    const float* bias   = (const float*)d_in[3];
    float* out          = (float*)d_out;

    qcnn_hetero<<<B_SZ + NPREP, NT>>>(inputs, params, W, bias, out);
}

// round 17
// speedup vs baseline: 1.2679x; 1.2679x over previous
#include <cuda_runtime.h>
#include <math_constants.h>
#include <cstdint>

// Problem: B=128, L=4096, FILTER_SIZE=2, N_QUBITS=4, 10 classes.
// Analytic reduction: expval_k(b,ol) = K_k * g(b,ol),
//   K_k = cos(p_k1)cos(p_k2)cos(p_k3)   (CNOT ring conjugates Z0 -> Z1Z2Z3)
//   g   = cos(x[ol,1]) * cos(x[ol+1,0]) * cos(x[ol+1,1])
// logits[j] = bias[j] + sum_ol g(ol)*(K0*W[2ol,j]+K1*W[2ol+1,j]); softmax.
//
// R4 two-kernel structure (proven fastest across 12 structural variants),
// with main's lane-31 shuffle/branch path replaced by a 3rd coalesced
// LDG.128 and Wp loads hoisted above the cos chain.
#define OLP    4096
#define NCLS   10
#define B_SZ   128
#define NT     1024
#define NWARP  (NT / 32)
#define W_F4   20475          // float4 count of W (8190*10 floats)

// Folded, TRANSPOSED weights d_Wp[j*OLP + ol]; column 4095 folds to zero
// (its W rows 8190/8191 are OOB -> staged as zero in prep).
__device__ __align__(16) float d_Wp[NCLS * OLP];

// ---------------------------------------------------------------------------
// Prep: fold+transpose W into d_Wp. 32 blocks x 256 threads (proven).
// ---------------------------------------------------------------------------
__global__ __launch_bounds__(256) void qcnn_prep(const float* __restrict__ params,
                                                 const float* __restrict__ W)
{
    __shared__ float sw[2560];
    const int bid = blockIdx.x, tid = threadIdx.x;

    const float4* w4 = (const float4*)W;
    const int f4base = bid * 640;
#pragma unroll
    for (int k = 0; k < 3; ++k) {
        int li = tid + k * 256;
        if (li < 640) {
            int gi = f4base + li;
            float4 v = (gi < W_F4) ? w4[gi] : make_float4(0.f, 0.f, 0.f, 0.f);
            *(float4*)&sw[4 * li] = v;
        }
    }
    __syncthreads();

    if (tid < 128) {
        float K0 = __cosf(params[1]) * __cosf(params[2]) * __cosf(params[3]);
        float K1 = __cosf(params[5]) * __cosf(params[6]) * __cosf(params[7]);
        int ol = bid * 128 + tid;
        const float* r = &sw[20 * tid];          // rows 2ol, 2ol+1 (10 f each)
#pragma unroll
        for (int j = 0; j < NCLS; ++j)
            d_Wp[j * OLP + ol] = fmaf(K1, r[10 + j], K0 * r[j]);
    }
}

// ---------------------------------------------------------------------------
// Main: one block (1024 threads) per batch row, 4 windows per thread.
// 3 coalesced x LDG.128 per thread (no shuffles, no divergent lane-31 path);
// first Wp loads hoisted so their L2 latency hides behind the cos chain.
// ---------------------------------------------------------------------------
__global__ __launch_bounds__(NT, 1) void qcnn_main(const float* __restrict__ x,
                                                   const float* __restrict__ bias,
                                                   float* __restrict__ out)
{
    __shared__ float sred[NWARP][NCLS];

    const int b   = blockIdx.x;
    const int tid = threadIdx.x;

    // ---- x pairs 4t..4t+5 via 3 coalesced float4 (v2 clamped for tid=1023;
    // its 4th window is the zero-weight pad, so the value is irrelevant)
    const float* xr = x + (size_t)b * OLP * 2;
    const float4* row4 = (const float4*)xr;
    const int i2 = (2 * tid + 2 < 2048) ? (2 * tid + 2) : 2047;
    float4 v0 = row4[2 * tid];
    float4 v1 = row4[2 * tid + 1];
    float4 v2 = row4[i2];

    // ---- hoist first Wp loads: L2 latency drains behind the cos chain
    const float4* Wp4 = (const float4*)d_Wp;
    float4 w0 = Wp4[0 * (OLP / 4) + tid];
    float4 w1 = Wp4[1 * (OLP / 4) + tid];

    // s1[i]=cos(x1), h[i]=cos(x0)*s1[i];  g_k = s1[k]*h[k+1]
    float s1_0 = __cosf(v0.y);
    float s1_1 = __cosf(v0.w), h1 = __cosf(v0.z) * s1_1;
    float s1_2 = __cosf(v1.y), h2 = __cosf(v1.x) * s1_2;
    float s1_3 = __cosf(v1.w), h3 = __cosf(v1.z) * s1_3;
    float h4   = __cosf(v2.x) * __cosf(v2.y);
    float g0 = s1_0 * h1;
    float g1 = s1_1 * h2;
    float g2 = s1_2 * h3;
    float g3 = s1_3 * h4;            // tid=1023: multiplied by zero Wp column

    // ---- dot with folded weights: 10 coalesced, L2-hot LDG.128 (MLP=10)
    float acc[NCLS];
    {
        float a;
        a = g0 * w0.x; a = fmaf(g1, w0.y, a);
        a = fmaf(g2, w0.z, a); a = fmaf(g3, w0.w, a);
        acc[0] = a;
        a = g0 * w1.x; a = fmaf(g1, w1.y, a);
        a = fmaf(g2, w1.z, a); a = fmaf(g3, w1.w, a);
        acc[1] = a;
    }
#pragma unroll
    for (int j = 2; j < NCLS; ++j) {
        float4 w = Wp4[j * (OLP / 4) + tid];
        float a;
        a = g0 * w.x;
        a = fmaf(g1, w.y, a);
        a = fmaf(g2, w.z, a);
        a = fmaf(g3, w.w, a);
        acc[j] = a;
    }

    // ---- reduce 1024 threads -> 10 logits (proven butterfly)
#pragma unroll
    for (int j = 0; j < NCLS; ++j) {
#pragma unroll
        for (int off = 16; off; off >>= 1)
            acc[j] += __shfl_xor_sync(0xFFFFFFFFu, acc[j], off);
    }
    const int warp = tid >> 5, lane = tid & 31;
    if (lane == 0) {
#pragma unroll
        for (int j = 0; j < NCLS; ++j) sred[warp][j] = acc[j];
    }
    __syncthreads();

    // ---- final reduce + softmax in warp 0 (lanes 0..9 own one class)
    if (tid < 32) {
        float logit = -CUDART_INF_F;
        if (tid < NCLS) {
            logit = bias[tid];
#pragma unroll
            for (int w = 0; w < NWARP; ++w) logit += sred[w][tid];
        }
        float mx = logit;
#pragma unroll
        for (int off = 16; off; off >>= 1)
            mx = fmaxf(mx, __shfl_xor_sync(0xFFFFFFFFu, mx, off));
        float e = (tid < NCLS) ? __expf(logit - mx) : 0.0f;
        float s = e;
#pragma unroll
        for (int off = 16; off; off >>= 1)
            s += __shfl_xor_sync(0xFFFFFFFFu, s, off);
        if (tid < NCLS) out[b * NCLS + tid] = e / s;
    }
}

// Inputs (metadata order): inputs(128*4096*2 f32), params(8 f32),
//                          W(8190*10 f32), b(10 f32). Output: (128*10) f32.
extern "C" void kernel_launch(void* const* d_in, const int* in_sizes, int n_in,
                              void* d_out, int out_size)
{
    const float* inputs = (const float*)d_in[0];
    const float* params = (const float*)d_in[1];
    const float* W      = (const float*)d_in[2];
    const float* bias   = (const float*)d_in[3];
    float* out          = (float*)d_out;

    qcnn_prep<<<32, 256>>>(params, W);
    qcnn_main<<<B_SZ, NT>>>(inputs, bias, out);
}